// round 14
// baseline (speedup 1.0000x reference)
#include <cuda_runtime.h>
#include <cuda_fp16.h>
#include <math.h>

#define NN 100000
#define EE 1600000
#define FH 64      // input/hidden width
#define CC 40      // output classes
#define P3S 48     // padded layer-3 P row stride in halves (96 B = 3 sectors)

#define GEMM_BLOCKS ((NN + 127) / 128)     // 782
#define SCAT_BLOCKS ((EE / 4 + 255) / 256) // 1563

// ---------------- scratch (device globals; no allocation allowed) ----------
__device__ int   g_deg_out[NN];
__device__ int   g_deg_in[NN];
__device__ float g_invo[NN];
__device__ float g_invi[NN];
__device__ int   g_start[NN];              // CSR row start
__device__ int   g_pos[NN];                // bump cursor per row
__device__ unsigned g_csrc[EE];            // CSR col only (weights folded out)
__device__ unsigned int g_ctr;             // global bump counter
__device__ __half g_p[(size_t)NN * FH];    // fp16 GEMM output (invi-scaled)
__device__ __half g_xh[(size_t)NN * FH];   // fp16 relu'd SpMM output (next GEMM in)
__device__ uint2  g_wf1[8 * 4 * 32];       // W1 fragment-major: [nt][ks][lane]
__device__ uint2  g_wf2[8 * 4 * 32];       // W2 fragment-major
__device__ uint2  g_wf3[5 * 4 * 32];       // Wo fragment-major (NT=5)

// ---------------- helpers ----------------------------------------------------
__device__ __forceinline__ unsigned smem_u32(const void* p) {
    return (unsigned)__cvta_generic_to_shared(p);
}
__device__ __forceinline__ void ldmatrix_x4(unsigned& a0, unsigned& a1,
                                            unsigned& a2, unsigned& a3,
                                            unsigned addr) {
    asm volatile("ldmatrix.sync.aligned.m8n8.x4.shared.b16 {%0,%1,%2,%3}, [%4];"
                 : "=r"(a0), "=r"(a1), "=r"(a2), "=r"(a3) : "r"(addr));
}
__device__ __forceinline__ void mma16816(float c[4], unsigned a0, unsigned a1,
                                         unsigned a2, unsigned a3,
                                         unsigned b0, unsigned b1) {
    asm volatile(
        "mma.sync.aligned.m16n8k16.row.col.f32.f16.f16.f32 "
        "{%0,%1,%2,%3}, {%4,%5,%6,%7}, {%8,%9}, {%0,%1,%2,%3};\n"
        : "+f"(c[0]), "+f"(c[1]), "+f"(c[2]), "+f"(c[3])
        : "r"(a0), "r"(a1), "r"(a2), "r"(a3), "r"(b0), "r"(b1));
}

// ---------------- zero + weight-fragment precompute ---------------------------
__global__ void zero_kernel(const float* __restrict__ W1,
                            const float* __restrict__ W2,
                            const float* __restrict__ W3) {
    int i = blockIdx.x * blockDim.x + threadIdx.x;
    if (i < NN) { g_deg_out[i] = 0; g_deg_in[i] = 0; }
    if (i == 0) g_ctr = 0u;
    if (blockIdx.x < 3) {
        const float* Ws = (blockIdx.x == 0) ? W1 : (blockIdx.x == 1) ? W2 : W3;
        uint2* dst = (blockIdx.x == 0) ? g_wf1 : (blockIdx.x == 1) ? g_wf2 : g_wf3;
        int outw = (blockIdx.x == 2) ? CC : FH;
        int nfr = (outw / 8) * 4 * 32;
        for (int idx = threadIdx.x; idx < nfr; idx += blockDim.x) {
            int lane = idx & 31;
            int ksnt = idx >> 5;
            int ks = ksnt & 3, nt = ksnt >> 2;
            int g = lane >> 2, tg = lane & 3;
            int n = nt * 8 + g;
            int k0 = ks * 16 + tg * 2;
            __half2 lo = __floats2half2_rn(Ws[k0 * outw + n], Ws[(k0 + 1) * outw + n]);
            __half2 hi = __floats2half2_rn(Ws[(k0 + 8) * outw + n], Ws[(k0 + 9) * outw + n]);
            uint2 v;
            v.x = *(unsigned*)&lo;
            v.y = *(unsigned*)&hi;
            dst[idx] = v;
        }
    }
}

// ---------------- degree histogram (4 edges/thread, int4 loads) --------------
__global__ void hist_kernel(const int4* __restrict__ row4, const int4* __restrict__ col4) {
    int q = blockIdx.x * blockDim.x + threadIdx.x;
    if (q >= EE / 4) return;
    int4 r = row4[q];
    int4 c = col4[q];
    atomicAdd(&g_deg_out[r.x], 1); atomicAdd(&g_deg_out[r.y], 1);
    atomicAdd(&g_deg_out[r.z], 1); atomicAdd(&g_deg_out[r.w], 1);
    atomicAdd(&g_deg_in[c.x], 1);  atomicAdd(&g_deg_in[c.y], 1);
    atomicAdd(&g_deg_in[c.z], 1);  atomicAdd(&g_deg_in[c.w], 1);
}

// ---------------- range assignment (warp-aggregated bump alloc) + inv degs --
__global__ void ranges_kernel() {
    int i = blockIdx.x * blockDim.x + threadIdx.x;
    int lane = threadIdx.x & 31;
    int d = (i < NN) ? g_deg_out[i] : 0;
    int incl = d;
#pragma unroll
    for (int o = 1; o < 32; o <<= 1) {
        int v = __shfl_up_sync(0xffffffffu, incl, o);
        if (lane >= o) incl += v;
    }
    int total = __shfl_sync(0xffffffffu, incl, 31);
    unsigned int base = 0;
    if (lane == 31) base = atomicAdd(&g_ctr, (unsigned int)total);
    base = __shfl_sync(0xffffffffu, base, 31);
    if (i < NN) {
        int st = (int)base + (incl - d);
        g_start[i] = st;
        g_pos[i]   = st;
        int di = g_deg_in[i];
        g_invo[i] = (d  > 0) ? rsqrtf((float)d)  : 0.f;
        g_invi[i] = (di > 0) ? rsqrtf((float)di) : 0.f;
    }
}

// ---------------- GEMM body (128-row tile) ------------------------------------
template <int OUT, int PSTRIDE, bool F32IN>
__device__ __forceinline__ void gemm_body(char* sA, int bid, int tid,
                                          const void* __restrict__ Xin,
                                          const uint2* __restrict__ Wf,
                                          __half* __restrict__ P) {
    const int w = tid >> 5, lane = tid & 31;
    const int row0 = bid * 128;
    constexpr int NT = OUT / 8;

    if (F32IN) {
        const float4* X4 = (const float4*)Xin;
#pragma unroll
        for (int i = 0; i < 8; i++) {
            int idx = tid + i * 256;
            int row = idx >> 4, j = idx & 15;
            int grow = row0 + row;
            float4 v = make_float4(0.f, 0.f, 0.f, 0.f);
            if (grow < NN) v = X4[(size_t)grow * 16 + j];
            __half2 h0 = __floats2half2_rn(v.x, v.y);
            __half2 h1 = __floats2half2_rn(v.z, v.w);
            int chunk = j >> 1, sub = (j & 1) * 8;
            uint2* dst = (uint2*)(sA + row * 128 + ((chunk ^ (row & 7)) << 4) + sub);
            *dst = make_uint2(*(unsigned*)&h0, *(unsigned*)&h1);
        }
    } else {
        const uint4* X4 = (const uint4*)Xin;
#pragma unroll
        for (int i = 0; i < 4; i++) {
            int idx = tid + i * 256;
            int row = idx >> 3, chunk = idx & 7;
            int grow = row0 + row;
            uint4 v = make_uint4(0u, 0u, 0u, 0u);
            if (grow < NN) v = X4[(size_t)grow * 8 + chunk];
            *(uint4*)(sA + row * 128 + ((chunk ^ (row & 7)) << 4)) = v;
        }
    }
    __syncthreads();

    const int lrow0 = w * 16;
    unsigned a[4][4];
#pragma unroll
    for (int ks = 0; ks < 4; ks++) {
        int lr = lrow0 + (lane & 15);
        int chunk = ks * 2 + (lane >> 4);
        unsigned addr = smem_u32(sA + lr * 128 + ((chunk ^ (lr & 7)) << 4));
        ldmatrix_x4(a[ks][0], a[ks][1], a[ks][2], a[ks][3], addr);
    }

    float acc[NT][4];
#pragma unroll
    for (int nt = 0; nt < NT; nt++) {
        acc[nt][0] = 0.f; acc[nt][1] = 0.f; acc[nt][2] = 0.f; acc[nt][3] = 0.f;
    }
#pragma unroll
    for (int ks = 0; ks < 4; ks++) {
#pragma unroll
        for (int nt = 0; nt < NT; nt++) {
            uint2 b = __ldg(Wf + (nt * 4 + ks) * 32 + lane);
            mma16816(acc[nt], a[ks][0], a[ks][1], a[ks][2], a[ks][3], b.x, b.y);
        }
    }

    const int g = lane >> 2, tg = lane & 3;
    const int rl1 = lrow0 + g, rl2 = lrow0 + g + 8;
    const int gr1 = row0 + rl1, gr2 = row0 + rl2;
    const float inv1 = (gr1 < NN) ? g_invi[gr1] : 0.f;
    const float inv2 = (gr2 < NN) ? g_invi[gr2] : 0.f;
    __syncthreads();
#pragma unroll
    for (int nt = 0; nt < NT; nt++) {
        __half2 h1 = __floats2half2_rn(acc[nt][0] * inv1, acc[nt][1] * inv1);
        __half2 h2 = __floats2half2_rn(acc[nt][2] * inv2, acc[nt][3] * inv2);
        *(unsigned*)(sA + rl1 * 128 + ((nt ^ (rl1 & 7)) << 4) + tg * 4) = *(unsigned*)&h1;
        *(unsigned*)(sA + rl2 * 128 + ((nt ^ (rl2 & 7)) << 4) + tg * 4) = *(unsigned*)&h2;
    }
    __syncthreads();

    if (PSTRIDE == 64) {
#pragma unroll
        for (int i = 0; i < 4; i++) {
            int idx = tid + i * 256;
            int row = idx >> 3, chunk = idx & 7;
            int grow = row0 + row;
            if (grow < NN) {
                uint4 v = *(const uint4*)(sA + row * 128 + ((chunk ^ (row & 7)) << 4));
                *(uint4*)((char*)P + (size_t)grow * 128 + chunk * 16) = v;
            }
        }
    } else {
#pragma unroll
        for (int i = 0; i < 3; i++) {
            int idx = tid + i * 256;
            int row = idx / 6, c = idx % 6;
            int grow = row0 + row;
            if (grow < NN) {
                uint4 v = *(const uint4*)(sA + row * 128 + ((c ^ (row & 7)) << 4));
                *(uint4*)((char*)P + (size_t)grow * 96 + c * 16) = v;
            }
        }
    }
}

// ---------------- standalone GEMM kernel (layers 2, 3) -----------------------
template <int OUT, int PSTRIDE, bool F32IN>
__global__ __launch_bounds__(256) void gemm_mma_kernel(
        const void* __restrict__ Xin,
        const uint2* __restrict__ Wf,
        __half* __restrict__ P) {
    __shared__ __align__(16) char sA[128 * 128];
    gemm_body<OUT, PSTRIDE, F32IN>(sA, blockIdx.x, threadIdx.x, Xin, Wf, P);
}

// ---------------- FUSED: gemm1 (blocks [0,GEMM_BLOCKS)) + scatter (rest) -----
__global__ __launch_bounds__(256) void gemm1_scatter_kernel(
        const void* __restrict__ Xin,
        const uint2* __restrict__ Wf,
        __half* __restrict__ P,
        const int4* __restrict__ row4,
        const int4* __restrict__ col4) {
    __shared__ __align__(16) char sA[128 * 128];
    if (blockIdx.x < GEMM_BLOCKS) {
        gemm_body<FH, FH, true>(sA, blockIdx.x, threadIdx.x, Xin, Wf, P);
    } else {
        int q = (blockIdx.x - GEMM_BLOCKS) * 256 + threadIdx.x;
        if (q < EE / 4) {
            int4 r = row4[q];
            int4 c = col4[q];
            g_csrc[atomicAdd(&g_pos[r.x], 1)] = (unsigned)c.x;
            g_csrc[atomicAdd(&g_pos[r.y], 1)] = (unsigned)c.y;
            g_csrc[atomicAdd(&g_pos[r.z], 1)] = (unsigned)c.z;
            g_csrc[atomicAdd(&g_pos[r.w], 1)] = (unsigned)c.w;
        }
    }
}

// ---------------- quarter-warp gather SpMM, width 64 --------------------------
// 8-lane quarters: one LDG.128 warp-instruction covers 4 edges (half the load
// instructions of the half-warp scheme, same bytes). Lane l8 owns features
// [8*l8, 8*l8+8). Cross-quarter combine via xor-8 / xor-16 shuffles.
__device__ __forceinline__ void acc8(float* a, uint4 v) {
    __half2* h = (__half2*)&v;
#pragma unroll
    for (int j = 0; j < 4; j++) {
        float2 f = __half22float2(h[j]);
        a[2 * j]     += f.x;
        a[2 * j + 1] += f.y;
    }
}

template <bool WRITE32>
__global__ void spmm64_kernel(const uint4* __restrict__ P,   // rows of 8 uint4
                              const float* __restrict__ bias,
                              float* __restrict__ Y) {
    int n = (blockIdx.x * blockDim.x + threadIdx.x) >> 5;
    int lane = threadIdx.x & 31;
    if (n >= NN) return;
    int s = g_start[n];
    int d = g_deg_out[n];
    const int quarter = lane >> 3;      // 0..3
    const int l8 = lane & 7;            // 0..7
    const unsigned* cs = g_csrc + s;
    float a[8] = {0.f, 0.f, 0.f, 0.f, 0.f, 0.f, 0.f, 0.f};
    int e = 0;
    for (; e + 16 <= d; e += 16) {      // 16 edges: 4 LDG.128 in flight
        unsigned c[4];
#pragma unroll
        for (int i = 0; i < 4; i++) c[i] = cs[e + 4 * i + quarter];
        uint4 v[4];
#pragma unroll
        for (int i = 0; i < 4; i++) v[i] = __ldg(P + c[i] * 8u + l8);
#pragma unroll
        for (int i = 0; i < 4; i++) acc8(a, v[i]);
    }
    if (e + 8 <= d) {                   // 8 edges: 2 LDG.128
        unsigned c0 = cs[e + quarter];
        unsigned c1 = cs[e + 4 + quarter];
        uint4 v0 = __ldg(P + c0 * 8u + l8);
        uint4 v1 = __ldg(P + c1 * 8u + l8);
        acc8(a, v0);
        acc8(a, v1);
        e += 8;
    }
    if (e + 4 <= d) {                   // 4 edges: 1 LDG.128
        unsigned c0 = cs[e + quarter];
        uint4 v0 = __ldg(P + c0 * 8u + l8);
        acc8(a, v0);
        e += 4;
    }
    if (e < d && quarter < d - e) {     // 1-3 leftover edges
        unsigned c0 = cs[e + quarter];
        uint4 v0 = __ldg(P + c0 * 8u + l8);
        acc8(a, v0);
    }
    // cross-quarter combine
#pragma unroll
    for (int j = 0; j < 8; j++) {
        a[j] += __shfl_xor_sync(0xffffffffu, a[j], 8);
        a[j] += __shfl_xor_sync(0xffffffffu, a[j], 16);
    }
    if (quarter == 0) {
        float inv = g_invo[n];
        const float4 b0 = *reinterpret_cast<const float4*>(bias + 8 * l8);
        const float4 b1 = *reinterpret_cast<const float4*>(bias + 8 * l8 + 4);
        float r[8];
        r[0] = fmaf(inv, a[0], b0.x); r[1] = fmaf(inv, a[1], b0.y);
        r[2] = fmaf(inv, a[2], b0.z); r[3] = fmaf(inv, a[3], b0.w);
        r[4] = fmaf(inv, a[4], b1.x); r[5] = fmaf(inv, a[5], b1.y);
        r[6] = fmaf(inv, a[6], b1.z); r[7] = fmaf(inv, a[7], b1.w);
        if (WRITE32) {
            *reinterpret_cast<float4*>(Y + (size_t)n * FH + 8 * l8) =
                make_float4(r[0], r[1], r[2], r[3]);
            *reinterpret_cast<float4*>(Y + (size_t)n * FH + 8 * l8 + 4) =
                make_float4(r[4], r[5], r[6], r[7]);
        }
        __half2 q0 = __floats2half2_rn(fmaxf(r[0], 0.f), fmaxf(r[1], 0.f));
        __half2 q1 = __floats2half2_rn(fmaxf(r[2], 0.f), fmaxf(r[3], 0.f));
        __half2 q2 = __floats2half2_rn(fmaxf(r[4], 0.f), fmaxf(r[5], 0.f));
        __half2 q3 = __floats2half2_rn(fmaxf(r[6], 0.f), fmaxf(r[7], 0.f));
        uint4 q = make_uint4(*(unsigned*)&q0, *(unsigned*)&q1,
                             *(unsigned*)&q2, *(unsigned*)&q3);
        *reinterpret_cast<uint4*>(g_xh + (size_t)n * FH + 8 * l8) = q;
    }
}

// ---------------- gather SpMM width 40 + log-softmax (exact R9 structure) ----
__global__ void spmm40_lsm_kernel(const __half2* __restrict__ P,
                                  const float* __restrict__ bias,
                                  float* __restrict__ O) {
    int n = (blockIdx.x * blockDim.x + threadIdx.x) >> 5;
    int lane = threadIdx.x & 31;
    if (n >= NN) return;
    int s = g_start[n];
    int d = g_deg_out[n];
    const bool act = (lane < CC / 2);
    float a0 = 0.f, a1 = 0.f, b0 = 0.f, b1 = 0.f;
    const unsigned* cs = g_csrc + s;
    int e = 0;
    for (; e + 8 <= d; e += 8) {
        unsigned c[8];
#pragma unroll
        for (int i = 0; i < 8; i++) c[i] = cs[e + i];
        if (act) {
            float2 v[8];
#pragma unroll
            for (int i = 0; i < 8; i++)
                v[i] = __half22float2(__ldg(P + c[i] * (unsigned)(P3S / 2) + lane));
#pragma unroll
            for (int i = 0; i < 8; i += 2) {
                a0 += v[i].x;     a1 += v[i].y;
                b0 += v[i + 1].x; b1 += v[i + 1].y;
            }
        }
    }
    for (; e < d; e++) {
        unsigned c0 = cs[e];
        if (act) {
            float2 v0 = __half22float2(__ldg(P + c0 * (unsigned)(P3S / 2) + lane));
            a0 += v0.x; a1 += v0.y;
        }
    }
    a0 += b0; a1 += b1;
    float inv = g_invo[n];
    float t0 = act ? fmaf(inv, a0, bias[2 * lane])     : 0.f;
    float t1 = act ? fmaf(inv, a1, bias[2 * lane + 1]) : 0.f;
    float m = act ? fmaxf(t0, t1) : -INFINITY;
#pragma unroll
    for (int o = 16; o; o >>= 1) m = fmaxf(m, __shfl_xor_sync(0xffffffffu, m, o));
    float sum = act ? (expf(t0 - m) + expf(t1 - m)) : 0.f;
#pragma unroll
    for (int o = 16; o; o >>= 1) sum += __shfl_xor_sync(0xffffffffu, sum, o);
    float ls = m + logf(sum);
    if (act) {
        *reinterpret_cast<float2*>(O + (size_t)n * CC + 2 * lane) =
            make_float2(t0 - ls, t1 - ls);
    }
}

// ---------------- launch -----------------------------------------------------
extern "C" void kernel_launch(void* const* d_in, const int* in_sizes, int n_in,
                              void* d_out, int out_size) {
    const float* x   = (const float*)d_in[0];
    const int*   ei  = (const int*)d_in[1];
    const int4*  row4 = (const int4*)ei;
    const int4*  col4 = (const int4*)(ei + EE);
    const float* W1s = (const float*)d_in[2];
    const float* b1s = (const float*)d_in[3];
    const float* W2s = (const float*)d_in[6];
    const float* b2s = (const float*)d_in[7];
    const float* Wos = (const float*)d_in[10];
    const float* bos = (const float*)d_in[11];

    float* out = (float*)d_out;
    float* h   = out;                       // [N, 64]
    float* lsm = out + (size_t)NN * FH;     // [N, 40]

    __half *pp, *pxh;
    uint2 *pw1, *pw2, *pw3;
    cudaGetSymbolAddress((void**)&pp,  g_p);
    cudaGetSymbolAddress((void**)&pxh, g_xh);
    cudaGetSymbolAddress((void**)&pw1, g_wf1);
    cudaGetSymbolAddress((void**)&pw2, g_wf2);
    cudaGetSymbolAddress((void**)&pw3, g_wf3);

    const int T = 256;
    const int WARPS_GRID = (NN * 32 + T - 1) / T;
    const int Q = EE / 4;

    // ---- CSR build; gemm1 fused with scatter (independent after ranges) ----
    zero_kernel<<<(NN + T - 1) / T, T>>>(W1s, W2s, Wos);
    hist_kernel<<<(Q + T - 1) / T, T>>>(row4, col4);
    ranges_kernel<<<(NN + T - 1) / T, T>>>();
    gemm1_scatter_kernel<<<GEMM_BLOCKS + SCAT_BLOCKS, 256>>>(x, pw1, pp, row4, col4);

    // ---- layer 1 aggregate ----
    spmm64_kernel<false><<<WARPS_GRID, T>>>((const uint4*)pp, b1s, h);
    // ---- layer 2 ----
    gemm_mma_kernel<FH, FH, false><<<(NN + 127) / 128, 256>>>(pxh, pw2, pp);
    spmm64_kernel<true><<<WARPS_GRID, T>>>((const uint4*)pp, b2s, h);
    // ---- layer 3 ----
    gemm_mma_kernel<CC, P3S, false><<<(NN + 127) / 128, 256>>>(pxh, pw3, pp);
    spmm40_lsm_kernel<<<WARPS_GRID, T>>>((const __half2*)pp, bos, lsm);
}

// round 15
// speedup vs baseline: 1.5131x; 1.5131x over previous
#include <cuda_runtime.h>
#include <cuda_fp16.h>
#include <math.h>

#define NN 100000
#define EE 1600000
#define FH 64      // input/hidden width
#define CC 40      // output classes
#define P3S 48     // padded layer-3 P row stride in halves (96 B = 3 sectors)

#define GEMM_BLOCKS ((NN + 127) / 128)     // 782

// ---------------- scratch (device globals; no allocation allowed) ----------
__device__ int   g_deg_out[NN];
__device__ int   g_deg_in[NN];
__device__ float g_invo[NN];
__device__ float g_invi[NN];
__device__ int   g_start[NN];              // CSR row start
__device__ int   g_pos[NN];                // bump cursor per row
__device__ unsigned g_csrc[EE];            // CSR col only (weights folded out)
__device__ unsigned int g_ctr;             // global bump counter
__device__ __half g_p[(size_t)NN * FH];    // fp16 GEMM output (invi-scaled)
__device__ __half g_xh[(size_t)NN * FH];   // fp16 relu'd SpMM output (next GEMM in)
__device__ uint2  g_wf1[8 * 4 * 32];       // W1 fragment-major: [nt][ks][lane]
__device__ uint2  g_wf2[8 * 4 * 32];       // W2 fragment-major
__device__ uint2  g_wf3[5 * 4 * 32];       // Wo fragment-major (NT=5)

// ---------------- helpers ----------------------------------------------------
__device__ __forceinline__ unsigned smem_u32(const void* p) {
    return (unsigned)__cvta_generic_to_shared(p);
}
__device__ __forceinline__ void ldmatrix_x4(unsigned& a0, unsigned& a1,
                                            unsigned& a2, unsigned& a3,
                                            unsigned addr) {
    asm volatile("ldmatrix.sync.aligned.m8n8.x4.shared.b16 {%0,%1,%2,%3}, [%4];"
                 : "=r"(a0), "=r"(a1), "=r"(a2), "=r"(a3) : "r"(addr));
}
__device__ __forceinline__ void mma16816(float c[4], unsigned a0, unsigned a1,
                                         unsigned a2, unsigned a3,
                                         unsigned b0, unsigned b1) {
    asm volatile(
        "mma.sync.aligned.m16n8k16.row.col.f32.f16.f16.f32 "
        "{%0,%1,%2,%3}, {%4,%5,%6,%7}, {%8,%9}, {%0,%1,%2,%3};\n"
        : "+f"(c[0]), "+f"(c[1]), "+f"(c[2]), "+f"(c[3])
        : "r"(a0), "r"(a1), "r"(a2), "r"(a3), "r"(b0), "r"(b1));
}

// ---------------- zero + weight-fragment precompute ---------------------------
__global__ void zero_kernel(const float* __restrict__ W1,
                            const float* __restrict__ W2,
                            const float* __restrict__ W3) {
    int i = blockIdx.x * blockDim.x + threadIdx.x;
    if (i < NN) { g_deg_out[i] = 0; g_deg_in[i] = 0; }
    if (i == 0) g_ctr = 0u;
    if (blockIdx.x < 3) {
        const float* Ws = (blockIdx.x == 0) ? W1 : (blockIdx.x == 1) ? W2 : W3;
        uint2* dst = (blockIdx.x == 0) ? g_wf1 : (blockIdx.x == 1) ? g_wf2 : g_wf3;
        int outw = (blockIdx.x == 2) ? CC : FH;
        int nfr = (outw / 8) * 4 * 32;
        for (int idx = threadIdx.x; idx < nfr; idx += blockDim.x) {
            int lane = idx & 31;
            int ksnt = idx >> 5;
            int ks = ksnt & 3, nt = ksnt >> 2;
            int g = lane >> 2, tg = lane & 3;
            int n = nt * 8 + g;
            int k0 = ks * 16 + tg * 2;
            __half2 lo = __floats2half2_rn(Ws[k0 * outw + n], Ws[(k0 + 1) * outw + n]);
            __half2 hi = __floats2half2_rn(Ws[(k0 + 8) * outw + n], Ws[(k0 + 9) * outw + n]);
            uint2 v;
            v.x = *(unsigned*)&lo;
            v.y = *(unsigned*)&hi;
            dst[idx] = v;
        }
    }
}

// ---------------- degree histogram (4 edges/thread, int4 loads) --------------
__global__ void hist_kernel(const int4* __restrict__ row4, const int4* __restrict__ col4) {
    int q = blockIdx.x * blockDim.x + threadIdx.x;
    if (q >= EE / 4) return;
    int4 r = row4[q];
    int4 c = col4[q];
    atomicAdd(&g_deg_out[r.x], 1); atomicAdd(&g_deg_out[r.y], 1);
    atomicAdd(&g_deg_out[r.z], 1); atomicAdd(&g_deg_out[r.w], 1);
    atomicAdd(&g_deg_in[c.x], 1);  atomicAdd(&g_deg_in[c.y], 1);
    atomicAdd(&g_deg_in[c.z], 1);  atomicAdd(&g_deg_in[c.w], 1);
}

// ---------------- range assignment (warp-aggregated bump alloc) + inv degs --
__global__ void ranges_kernel() {
    int i = blockIdx.x * blockDim.x + threadIdx.x;
    int lane = threadIdx.x & 31;
    int d = (i < NN) ? g_deg_out[i] : 0;
    int incl = d;
#pragma unroll
    for (int o = 1; o < 32; o <<= 1) {
        int v = __shfl_up_sync(0xffffffffu, incl, o);
        if (lane >= o) incl += v;
    }
    int total = __shfl_sync(0xffffffffu, incl, 31);
    unsigned int base = 0;
    if (lane == 31) base = atomicAdd(&g_ctr, (unsigned int)total);
    base = __shfl_sync(0xffffffffu, base, 31);
    if (i < NN) {
        int st = (int)base + (incl - d);
        g_start[i] = st;
        g_pos[i]   = st;
        int di = g_deg_in[i];
        g_invo[i] = (d  > 0) ? rsqrtf((float)d)  : 0.f;
        g_invi[i] = (di > 0) ? rsqrtf((float)di) : 0.f;
    }
}

// ---------------- GEMM body (128-row tile) ------------------------------------
template <int OUT, int PSTRIDE, bool F32IN>
__device__ __forceinline__ void gemm_body(char* sA, int bid, int tid,
                                          const void* __restrict__ Xin,
                                          const uint2* __restrict__ Wf,
                                          __half* __restrict__ P) {
    const int w = tid >> 5, lane = tid & 31;
    const int row0 = bid * 128;
    constexpr int NT = OUT / 8;

    if (F32IN) {
        const float4* X4 = (const float4*)Xin;
#pragma unroll
        for (int i = 0; i < 8; i++) {
            int idx = tid + i * 256;
            int row = idx >> 4, j = idx & 15;
            int grow = row0 + row;
            float4 v = make_float4(0.f, 0.f, 0.f, 0.f);
            if (grow < NN) v = X4[(size_t)grow * 16 + j];
            __half2 h0 = __floats2half2_rn(v.x, v.y);
            __half2 h1 = __floats2half2_rn(v.z, v.w);
            int chunk = j >> 1, sub = (j & 1) * 8;
            uint2* dst = (uint2*)(sA + row * 128 + ((chunk ^ (row & 7)) << 4) + sub);
            *dst = make_uint2(*(unsigned*)&h0, *(unsigned*)&h1);
        }
    } else {
        const uint4* X4 = (const uint4*)Xin;
#pragma unroll
        for (int i = 0; i < 4; i++) {
            int idx = tid + i * 256;
            int row = idx >> 3, chunk = idx & 7;
            int grow = row0 + row;
            uint4 v = make_uint4(0u, 0u, 0u, 0u);
            if (grow < NN) v = X4[(size_t)grow * 8 + chunk];
            *(uint4*)(sA + row * 128 + ((chunk ^ (row & 7)) << 4)) = v;
        }
    }
    __syncthreads();

    const int lrow0 = w * 16;
    unsigned a[4][4];
#pragma unroll
    for (int ks = 0; ks < 4; ks++) {
        int lr = lrow0 + (lane & 15);
        int chunk = ks * 2 + (lane >> 4);
        unsigned addr = smem_u32(sA + lr * 128 + ((chunk ^ (lr & 7)) << 4));
        ldmatrix_x4(a[ks][0], a[ks][1], a[ks][2], a[ks][3], addr);
    }

    float acc[NT][4];
#pragma unroll
    for (int nt = 0; nt < NT; nt++) {
        acc[nt][0] = 0.f; acc[nt][1] = 0.f; acc[nt][2] = 0.f; acc[nt][3] = 0.f;
    }
#pragma unroll
    for (int ks = 0; ks < 4; ks++) {
#pragma unroll
        for (int nt = 0; nt < NT; nt++) {
            uint2 b = __ldg(Wf + (nt * 4 + ks) * 32 + lane);
            mma16816(acc[nt], a[ks][0], a[ks][1], a[ks][2], a[ks][3], b.x, b.y);
        }
    }

    const int g = lane >> 2, tg = lane & 3;
    const int rl1 = lrow0 + g, rl2 = lrow0 + g + 8;
    const int gr1 = row0 + rl1, gr2 = row0 + rl2;
    const float inv1 = (gr1 < NN) ? g_invi[gr1] : 0.f;
    const float inv2 = (gr2 < NN) ? g_invi[gr2] : 0.f;
    __syncthreads();
#pragma unroll
    for (int nt = 0; nt < NT; nt++) {
        __half2 h1 = __floats2half2_rn(acc[nt][0] * inv1, acc[nt][1] * inv1);
        __half2 h2 = __floats2half2_rn(acc[nt][2] * inv2, acc[nt][3] * inv2);
        *(unsigned*)(sA + rl1 * 128 + ((nt ^ (rl1 & 7)) << 4) + tg * 4) = *(unsigned*)&h1;
        *(unsigned*)(sA + rl2 * 128 + ((nt ^ (rl2 & 7)) << 4) + tg * 4) = *(unsigned*)&h2;
    }
    __syncthreads();

    if (PSTRIDE == 64) {
#pragma unroll
        for (int i = 0; i < 4; i++) {
            int idx = tid + i * 256;
            int row = idx >> 3, chunk = idx & 7;
            int grow = row0 + row;
            if (grow < NN) {
                uint4 v = *(const uint4*)(sA + row * 128 + ((chunk ^ (row & 7)) << 4));
                *(uint4*)((char*)P + (size_t)grow * 128 + chunk * 16) = v;
            }
        }
    } else {
#pragma unroll
        for (int i = 0; i < 3; i++) {
            int idx = tid + i * 256;
            int row = idx / 6, c = idx % 6;
            int grow = row0 + row;
            if (grow < NN) {
                uint4 v = *(const uint4*)(sA + row * 128 + ((c ^ (row & 7)) << 4));
                *(uint4*)((char*)P + (size_t)grow * 96 + c * 16) = v;
            }
        }
    }
}

// ---------------- standalone GEMM kernel (layers 2, 3) -----------------------
template <int OUT, int PSTRIDE, bool F32IN>
__global__ __launch_bounds__(256) void gemm_mma_kernel(
        const void* __restrict__ Xin,
        const uint2* __restrict__ Wf,
        __half* __restrict__ P) {
    __shared__ __align__(16) char sA[128 * 128];
    gemm_body<OUT, PSTRIDE, F32IN>(sA, blockIdx.x, threadIdx.x, Xin, Wf, P);
}

// ---------------- FUSED: gemm1 + scatter, INTERLEAVED block mapping ----------
// bid % 3 == 0 -> gemm tile bid/3 (782 tiles); else scatter chunk
// 2*(bid/3) + (bid%3) - 1 (1564 slots covering 1563 chunks; last is guarded).
// Every scheduler wave gets a 1:2 gemm:scatter mix -> full co-residency of the
// DRAM-streaming GEMM and L2-atomic scatter.
__global__ __launch_bounds__(256) void gemm1_scatter_kernel(
        const void* __restrict__ Xin,
        const uint2* __restrict__ Wf,
        __half* __restrict__ P,
        const int4* __restrict__ row4,
        const int4* __restrict__ col4) {
    __shared__ __align__(16) char sA[128 * 128];
    const int bid = blockIdx.x;
    const int third = bid / 3, rem = bid % 3;
    if (rem == 0) {
        gemm_body<FH, FH, true>(sA, third, threadIdx.x, Xin, Wf, P);
    } else {
        int sid = 2 * third + rem - 1;
        int q = sid * 256 + threadIdx.x;
        if (q < EE / 4) {
            int4 r = row4[q];
            int4 c = col4[q];
            g_csrc[atomicAdd(&g_pos[r.x], 1)] = (unsigned)c.x;
            g_csrc[atomicAdd(&g_pos[r.y], 1)] = (unsigned)c.y;
            g_csrc[atomicAdd(&g_pos[r.z], 1)] = (unsigned)c.z;
            g_csrc[atomicAdd(&g_pos[r.w], 1)] = (unsigned)c.w;
        }
    }
}

// ---------------- half-warp gather SpMM, width 64 (exact R9/R12 structure) ---
__device__ __forceinline__ void acc4(float& a0, float& a1, float& a2, float& a3,
                                     uint2 v) {
    __half2 h0 = *reinterpret_cast<__half2*>(&v.x);
    __half2 h1 = *reinterpret_cast<__half2*>(&v.y);
    float2 f0 = __half22float2(h0);
    float2 f1 = __half22float2(h1);
    a0 += f0.x; a1 += f0.y; a2 += f1.x; a3 += f1.y;
}

template <bool WRITE32>
__global__ void spmm64_kernel(const uint2* __restrict__ P,   // rows of 16 uint2
                              const float* __restrict__ bias,
                              float* __restrict__ Y) {
    int n = (blockIdx.x * blockDim.x + threadIdx.x) >> 5;
    int lane = threadIdx.x & 31;
    if (n >= NN) return;
    int s = g_start[n];
    int d = g_deg_out[n];
    const int half = lane >> 4;
    const int l16  = lane & 15;
    const unsigned* cs = g_csrc + s;
    float a0 = 0.f, a1 = 0.f, a2 = 0.f, a3 = 0.f;
    int e = 0;
    for (; e + 16 <= d; e += 16) {
        unsigned c[8];
#pragma unroll
        for (int i = 0; i < 8; i++) c[i] = cs[e + 2 * i + half];
        uint2 v[8];
#pragma unroll
        for (int i = 0; i < 8; i++) v[i] = __ldg(P + c[i] * 16u + l16);
#pragma unroll
        for (int i = 0; i < 8; i++) acc4(a0, a1, a2, a3, v[i]);
    }
    if (e + 8 <= d) {
        unsigned c[4];
#pragma unroll
        for (int i = 0; i < 4; i++) c[i] = cs[e + 2 * i + half];
        uint2 v[4];
#pragma unroll
        for (int i = 0; i < 4; i++) v[i] = __ldg(P + c[i] * 16u + l16);
#pragma unroll
        for (int i = 0; i < 4; i++) acc4(a0, a1, a2, a3, v[i]);
        e += 8;
    }
    for (; e + 2 <= d; e += 2) {
        unsigned c = cs[e + half];
        uint2 v = __ldg(P + c * 16u + l16);
        acc4(a0, a1, a2, a3, v);
    }
    if (e < d && half == 0) {
        unsigned c = cs[e];
        uint2 v = __ldg(P + c * 16u + l16);
        acc4(a0, a1, a2, a3, v);
    }
    a0 += __shfl_xor_sync(0xffffffffu, a0, 16);
    a1 += __shfl_xor_sync(0xffffffffu, a1, 16);
    a2 += __shfl_xor_sync(0xffffffffu, a2, 16);
    a3 += __shfl_xor_sync(0xffffffffu, a3, 16);
    if (half == 0) {
        float inv = g_invo[n];
        const float4 bb = *reinterpret_cast<const float4*>(bias + 4 * l16);
        float r0 = fmaf(inv, a0, bb.x);
        float r1 = fmaf(inv, a1, bb.y);
        float r2 = fmaf(inv, a2, bb.z);
        float r3 = fmaf(inv, a3, bb.w);
        if (WRITE32) {
            *reinterpret_cast<float4*>(Y + (size_t)n * FH + 4 * l16) =
                make_float4(r0, r1, r2, r3);
        }
        __half2 q0 = __floats2half2_rn(fmaxf(r0, 0.f), fmaxf(r1, 0.f));
        __half2 q1 = __floats2half2_rn(fmaxf(r2, 0.f), fmaxf(r3, 0.f));
        uint2 q = make_uint2(*(unsigned*)&q0, *(unsigned*)&q1);
        *reinterpret_cast<uint2*>(g_xh + (size_t)n * FH + 4 * l16) = q;
    }
}

// ---------------- gather SpMM width 40 + log-softmax (exact R9/R12) ----------
__global__ void spmm40_lsm_kernel(const __half2* __restrict__ P,
                                  const float* __restrict__ bias,
                                  float* __restrict__ O) {
    int n = (blockIdx.x * blockDim.x + threadIdx.x) >> 5;
    int lane = threadIdx.x & 31;
    if (n >= NN) return;
    int s = g_start[n];
    int d = g_deg_out[n];
    const bool act = (lane < CC / 2);
    float a0 = 0.f, a1 = 0.f, b0 = 0.f, b1 = 0.f;
    const unsigned* cs = g_csrc + s;
    int e = 0;
    for (; e + 8 <= d; e += 8) {
        unsigned c[8];
#pragma unroll
        for (int i = 0; i < 8; i++) c[i] = cs[e + i];
        if (act) {
            float2 v[8];
#pragma unroll
            for (int i = 0; i < 8; i++)
                v[i] = __half22float2(__ldg(P + c[i] * (unsigned)(P3S / 2) + lane));
#pragma unroll
            for (int i = 0; i < 8; i += 2) {
                a0 += v[i].x;     a1 += v[i].y;
                b0 += v[i + 1].x; b1 += v[i + 1].y;
            }
        }
    }
    for (; e < d; e++) {
        unsigned c0 = cs[e];
        if (act) {
            float2 v0 = __half22float2(__ldg(P + c0 * (unsigned)(P3S / 2) + lane));
            a0 += v0.x; a1 += v0.y;
        }
    }
    a0 += b0; a1 += b1;
    float inv = g_invo[n];
    float t0 = act ? fmaf(inv, a0, bias[2 * lane])     : 0.f;
    float t1 = act ? fmaf(inv, a1, bias[2 * lane + 1]) : 0.f;
    float m = act ? fmaxf(t0, t1) : -INFINITY;
#pragma unroll
    for (int o = 16; o; o >>= 1) m = fmaxf(m, __shfl_xor_sync(0xffffffffu, m, o));
    float sum = act ? (expf(t0 - m) + expf(t1 - m)) : 0.f;
#pragma unroll
    for (int o = 16; o; o >>= 1) sum += __shfl_xor_sync(0xffffffffu, sum, o);
    float ls = m + logf(sum);
    if (act) {
        *reinterpret_cast<float2*>(O + (size_t)n * CC + 2 * lane) =
            make_float2(t0 - ls, t1 - ls);
    }
}

// ---------------- launch -----------------------------------------------------
extern "C" void kernel_launch(void* const* d_in, const int* in_sizes, int n_in,
                              void* d_out, int out_size) {
    const float* x   = (const float*)d_in[0];
    const int*   ei  = (const int*)d_in[1];
    const int4*  row4 = (const int4*)ei;
    const int4*  col4 = (const int4*)(ei + EE);
    const float* W1s = (const float*)d_in[2];
    const float* b1s = (const float*)d_in[3];
    const float* W2s = (const float*)d_in[6];
    const float* b2s = (const float*)d_in[7];
    const float* Wos = (const float*)d_in[10];
    const float* bos = (const float*)d_in[11];

    float* out = (float*)d_out;
    float* h   = out;                       // [N, 64]
    float* lsm = out + (size_t)NN * FH;     // [N, 40]

    __half *pp, *pxh;
    uint2 *pw1, *pw2, *pw3;
    cudaGetSymbolAddress((void**)&pp,  g_p);
    cudaGetSymbolAddress((void**)&pxh, g_xh);
    cudaGetSymbolAddress((void**)&pw1, g_wf1);
    cudaGetSymbolAddress((void**)&pw2, g_wf2);
    cudaGetSymbolAddress((void**)&pw3, g_wf3);

    const int T = 256;
    const int WARPS_GRID = (NN * 32 + T - 1) / T;
    const int Q = EE / 4;

    // ---- CSR build; gemm1 interleaved with scatter ----
    zero_kernel<<<(NN + T - 1) / T, T>>>(W1s, W2s, Wos);
    hist_kernel<<<(Q + T - 1) / T, T>>>(row4, col4);
    ranges_kernel<<<(NN + T - 1) / T, T>>>();
    gemm1_scatter_kernel<<<GEMM_BLOCKS * 3, 256>>>(x, pw1, pp, row4, col4);

    // ---- layer 1 aggregate ----
    spmm64_kernel<false><<<WARPS_GRID, T>>>((const uint2*)pp, b1s, h);
    // ---- layer 2 ----
    gemm_mma_kernel<FH, FH, false><<<(NN + 127) / 128, 256>>>(pxh, pw2, pp);
    spmm64_kernel<true><<<WARPS_GRID, T>>>((const uint2*)pp, b2s, h);
    // ---- layer 3 ----
    gemm_mma_kernel<CC, P3S, false><<<(NN + 127) / 128, 256>>>(pxh, pw3, pp);
    spmm40_lsm_kernel<<<WARPS_GRID, T>>>((const __half2*)pp, bos, lsm);
}